// round 3
// baseline (speedup 1.0000x reference)
#include <cuda_runtime.h>

#define B_ROWS 8192
#define D_IN   256
#define H1DIM  512
#define H2DIM  256
#define D_OUT  64

// Scratch (no cudaMalloc allowed) — 28 MB of __device__ globals.
__device__ float g_h1[B_ROWS * H1DIM];
__device__ float g_h2[B_ROWS * H2DIM];
__device__ float g_out[B_ROWS * D_OUT];
__device__ float g_normed[B_ROWS * D_OUT];

__device__ __forceinline__ float tanh_fast(float x) {
    // tanh(x) = 1 - 2/(e^{2x}+1); robust at both saturation ends.
    float e = __expf(2.0f * x);
    return 1.0f - 2.0f / (e + 1.0f);
}

// ---------------------------------------------------------------------------
// Generic fused GEMM: C[M,N] = act(A[M,K] @ W[N,K]^T + bias), all row-major.
// 16x16 thread grid, TMxTN register tile with STRIDED row assignment
// (row = t + 16*i) so shared reads are <=2-way conflicted with float4 loads.
// k is vectorized by 4 (float4 dot), natural [row][k] smem layout, no transpose.
// ---------------------------------------------------------------------------
template<int BM, int BN, int BK, int TM, int TN, bool TANH>
__global__ __launch_bounds__(256)
void gemm_bias_act(const float* __restrict__ A, const float* __restrict__ W,
                   const float* __restrict__ bias, float* __restrict__ C,
                   int M, int N, int K)
{
    constexpr int SK = BK + 4;          // pad keeps float4 alignment, spreads banks
    __shared__ float sA[BM * SK];
    __shared__ float sB[BN * SK];

    const int tid = threadIdx.x;
    const int tx  = tid & 15;
    const int ty  = tid >> 4;
    const int m0  = blockIdx.y * BM;
    const int n0  = blockIdx.x * BN;

    constexpr int C4 = BK / 4;               // float4 per smem row
    constexpr int LA = (BM * C4) / 256;      // float4 loads per thread (A)
    constexpr int LB = (BN * C4) / 256;      // float4 loads per thread (B)

    float acc[TM][TN];
#pragma unroll
    for (int i = 0; i < TM; i++)
#pragma unroll
        for (int j = 0; j < TN; j++) acc[i][j] = 0.0f;

#pragma unroll 1
    for (int k0 = 0; k0 < K; k0 += BK) {
        __syncthreads();
#pragma unroll
        for (int q = 0; q < LA; q++) {
            int id = tid + 256 * q;
            int r = id / C4, c = id % C4;
            *(float4*)&sA[r * SK + c * 4] =
                *(const float4*)&A[(size_t)(m0 + r) * K + k0 + c * 4];
        }
#pragma unroll
        for (int q = 0; q < LB; q++) {
            int id = tid + 256 * q;
            int r = id / C4, c = id % C4;
            *(float4*)&sB[r * SK + c * 4] =
                *(const float4*)&W[(size_t)(n0 + r) * K + k0 + c * 4];
        }
        __syncthreads();
#pragma unroll
        for (int c = 0; c < C4; c++) {
            float4 a[TM], b[TN];
#pragma unroll
            for (int ii = 0; ii < TM; ii++)
                a[ii] = *(const float4*)&sA[(ty + 16 * ii) * SK + c * 4];
#pragma unroll
            for (int jj = 0; jj < TN; jj++)
                b[jj] = *(const float4*)&sB[(tx + 16 * jj) * SK + c * 4];
#pragma unroll
            for (int ii = 0; ii < TM; ii++)
#pragma unroll
                for (int jj = 0; jj < TN; jj++) {
                    acc[ii][jj] += a[ii].x * b[jj].x;
                    acc[ii][jj] += a[ii].y * b[jj].y;
                    acc[ii][jj] += a[ii].z * b[jj].z;
                    acc[ii][jj] += a[ii].w * b[jj].w;
                }
        }
    }

    float bl[TN];
#pragma unroll
    for (int jj = 0; jj < TN; jj++) bl[jj] = bias[n0 + tx + 16 * jj];
#pragma unroll
    for (int ii = 0; ii < TM; ii++) {
        const int m = m0 + ty + 16 * ii;
#pragma unroll
        for (int jj = 0; jj < TN; jj++) {
            float v = acc[ii][jj] + bl[jj];
            if (TANH) v = tanh_fast(v);
            C[(size_t)m * N + n0 + tx + 16 * jj] = v;
        }
    }
}

// ---------------------------------------------------------------------------
// Row-normalize: normed[r] = out[r] / (||out[r]|| + 1e-12). One warp per row.
// ---------------------------------------------------------------------------
__global__ __launch_bounds__(256)
void normalize_kernel(const float* __restrict__ out, float* __restrict__ normed)
{
    const int row  = blockIdx.x * 8 + (threadIdx.x >> 5);
    const int lane = threadIdx.x & 31;
    float v0 = out[(size_t)row * D_OUT + lane];
    float v1 = out[(size_t)row * D_OUT + lane + 32];
    float s = v0 * v0 + v1 * v1;
#pragma unroll
    for (int off = 16; off > 0; off >>= 1)
        s += __shfl_xor_sync(0xffffffffu, s, off);
    float inv = 1.0f / (sqrtf(s) + 1e-12f);
    normed[(size_t)row * D_OUT + lane]      = v0 * inv;
    normed[(size_t)row * D_OUT + lane + 32] = v1 * inv;
}

// ---------------------------------------------------------------------------
// Pairwise fidelity + adjacency @ out, fully fused — adjacency never hits GMEM.
// One CTA owns 64 i-rows, loops over all 128 j-tiles of 64:
//   phase 1: 64x64 dot tile (FFMA, float4 over k)        -> d[4][4] per thread
//   phase 2: threshold (d^2 >= 0.9, i != j) -> shared bitmasks (atomicOr, rare)
//   phase 3: sparse gather: thread (i, 16-dim seg) walks mask bits, adds out_j.
// Result rows are exclusively owned -> plain stores, deterministic.
// ---------------------------------------------------------------------------
#define PAIR_SMEM_BYTES ((64*64 + 2*64*68) * 4 + 128 * 4)

__global__ __launch_bounds__(256)
void pair_adj_kernel(const float* __restrict__ normed,
                     const float* __restrict__ out,
                     float* __restrict__ result)
{
    extern __shared__ float sm[];
    float*    sNi   = sm;                       // [64][64]  stride 64 (broadcast reads)
    float*    sNj   = sm + 64 * 64;             // [64][68]  padded (strided reads)
    float*    sOutj = sNj + 64 * 68;            // [64][68]
    unsigned* sMask = (unsigned*)(sOutj + 64 * 68); // [64][2] bitmask words

    const int tid = threadIdx.x;
    const int tx  = tid & 15;
    const int ty  = tid >> 4;
    const int i0  = blockIdx.x * 64;

    // Load this CTA's 64 normalized i-rows once.
#pragma unroll
    for (int q = 0; q < 4; q++) {
        int id = tid + 256 * q;
        int r = id >> 4, c = id & 15;
        *(float4*)&sNi[r * 64 + c * 4] =
            *(const float4*)&normed[(size_t)(i0 + r) * 64 + c * 4];
    }

    float racc[16];
#pragma unroll
    for (int u = 0; u < 16; u++) racc[u] = 0.0f;
    const int irow = tid >> 2;           // accumulate-phase row (0..63)
    const int seg  = (tid & 3) * 16;     // owned 16-dim segment

#pragma unroll 1
    for (int jt = 0; jt < B_ROWS / 64; jt++) {
        const int j0 = jt * 64;
        __syncthreads();   // prior gather done; also covers initial sNi stores
#pragma unroll
        for (int q = 0; q < 4; q++) {
            int id = tid + 256 * q;
            int r = id >> 4, c = id & 15;
            *(float4*)&sNj[r * 68 + c * 4] =
                *(const float4*)&normed[(size_t)(j0 + r) * 64 + c * 4];
            *(float4*)&sOutj[r * 68 + c * 4] =
                *(const float4*)&out[(size_t)(j0 + r) * 64 + c * 4];
        }
        if (tid < 128) sMask[tid] = 0u;
        __syncthreads();

        // ---- dot tile: d[ii][jj] = <Ni[ty+16*ii], Nj[tx+16*jj]> ----
        float d[4][4];
#pragma unroll
        for (int ii = 0; ii < 4; ii++)
#pragma unroll
            for (int jj = 0; jj < 4; jj++) d[ii][jj] = 0.0f;
#pragma unroll
        for (int c = 0; c < 16; c++) {
            float4 a[4], b[4];
#pragma unroll
            for (int ii = 0; ii < 4; ii++)
                a[ii] = *(const float4*)&sNi[(ty + 16 * ii) * 64 + c * 4];
#pragma unroll
            for (int jj = 0; jj < 4; jj++)
                b[jj] = *(const float4*)&sNj[(tx + 16 * jj) * 68 + c * 4];
#pragma unroll
            for (int ii = 0; ii < 4; ii++)
#pragma unroll
                for (int jj = 0; jj < 4; jj++) {
                    d[ii][jj] += a[ii].x * b[jj].x;
                    d[ii][jj] += a[ii].y * b[jj].y;
                    d[ii][jj] += a[ii].z * b[jj].z;
                    d[ii][jj] += a[ii].w * b[jj].w;
                }
        }

        // ---- threshold -> bitmasks (atomics only when an edge exists) ----
#pragma unroll
        for (int ii = 0; ii < 4; ii++) {
            const int il = ty + 16 * ii;
            const int gi = i0 + il;
            unsigned w0 = 0u, w1 = 0u;
#pragma unroll
            for (int jj = 0; jj < 4; jj++) {
                const int jl = tx + 16 * jj;
                const float dv = d[ii][jj];
                const bool e = (dv * dv >= 0.9f) && (gi != (j0 + jl));
                const unsigned bit = e ? (1u << (jl & 31)) : 0u;
                if (jj < 2) w0 |= bit; else w1 |= bit;
            }
            if (w0) atomicOr(&sMask[il * 2 + 0], w0);
            if (w1) atomicOr(&sMask[il * 2 + 1], w1);
        }
        __syncthreads();

        // ---- sparse gather: racc[seg..seg+15] += sum over set bits ----
        unsigned mw0 = sMask[irow * 2 + 0];
        unsigned mw1 = sMask[irow * 2 + 1];
        while (mw0) {
            const int j = __ffs((int)mw0) - 1;
            mw0 &= mw0 - 1;
            const float* o = &sOutj[j * 68 + seg];
#pragma unroll
            for (int u = 0; u < 4; u++) {
                float4 v = *(const float4*)&o[u * 4];
                racc[u * 4 + 0] += v.x; racc[u * 4 + 1] += v.y;
                racc[u * 4 + 2] += v.z; racc[u * 4 + 3] += v.w;
            }
        }
        while (mw1) {
            const int j = 32 + __ffs((int)mw1) - 1;
            mw1 &= mw1 - 1;
            const float* o = &sOutj[j * 68 + seg];
#pragma unroll
            for (int u = 0; u < 4; u++) {
                float4 v = *(const float4*)&o[u * 4];
                racc[u * 4 + 0] += v.x; racc[u * 4 + 1] += v.y;
                racc[u * 4 + 2] += v.z; racc[u * 4 + 3] += v.w;
            }
        }
    }

    // Exclusive ownership: one thread per (row, segment). Plain stores.
    const int gi = i0 + irow;
#pragma unroll
    for (int u = 0; u < 4; u++) {
        float4 v = make_float4(racc[u * 4 + 0], racc[u * 4 + 1],
                               racc[u * 4 + 2], racc[u * 4 + 3]);
        *(float4*)&result[(size_t)gi * 64 + seg + u * 4] = v;
    }
}

// ---------------------------------------------------------------------------
extern "C" void kernel_launch(void* const* d_in, const int* in_sizes, int n_in,
                              void* d_out, int out_size)
{
    const float* x  = (const float*)d_in[0];
    const float* W1 = (const float*)d_in[1];
    const float* b1 = (const float*)d_in[2];
    const float* W2 = (const float*)d_in[3];
    const float* b2 = (const float*)d_in[4];
    const float* W3 = (const float*)d_in[5];
    const float* b3 = (const float*)d_in[6];
    float* result = (float*)d_out;

    float *h1, *h2, *o, *nr;
    cudaGetSymbolAddress((void**)&h1, g_h1);
    cudaGetSymbolAddress((void**)&h2, g_h2);
    cudaGetSymbolAddress((void**)&o,  g_out);
    cudaGetSymbolAddress((void**)&nr, g_normed);

    // L1: h1 = tanh(x @ W1^T + b1)   [8192,512]
    gemm_bias_act<128, 64, 32, 8, 4, true>
        <<<dim3(H1DIM / 64, B_ROWS / 128), 256>>>(x, W1, b1, h1, B_ROWS, H1DIM, D_IN);
    // L2: h2 = tanh(h1 @ W2^T + b2)  [8192,256]
    gemm_bias_act<128, 64, 32, 8, 4, true>
        <<<dim3(H2DIM / 64, B_ROWS / 128), 256>>>(h1, W2, b2, h2, B_ROWS, H2DIM, H1DIM);
    // L3: out = h2 @ W3^T + b3       [8192,64]
    gemm_bias_act<64, 64, 32, 4, 4, false>
        <<<dim3(D_OUT / 64, B_ROWS / 64), 256>>>(h2, W3, b3, o, B_ROWS, D_OUT, H2DIM);

    normalize_kernel<<<B_ROWS / 8, 256>>>(o, nr);

    cudaFuncSetAttribute(pair_adj_kernel,
                         cudaFuncAttributeMaxDynamicSharedMemorySize,
                         PAIR_SMEM_BYTES);
    pair_adj_kernel<<<B_ROWS / 64, 256, PAIR_SMEM_BYTES>>>(nr, o, result);
}

// round 5
// speedup vs baseline: 1.0209x; 1.0209x over previous
#include <cuda_runtime.h>

#define B_ROWS 8192
#define D_IN   256
#define H1DIM  512
#define H2DIM  256
#define D_OUT  64

// Scratch (no cudaMalloc allowed) — __device__ globals.
__device__ float g_h1[B_ROWS * H1DIM];
__device__ float g_h2[B_ROWS * H2DIM];
__device__ float g_out[B_ROWS * D_OUT];
__device__ float g_normed[B_ROWS * D_OUT];

using u64 = unsigned long long;

// Packed fp32x2 FMA: d = a*b + d elementwise on (lo,hi) float pairs.
// ptxas will NOT auto-fuse this from C++ — PTX only. 2x FFMA throughput.
__device__ __forceinline__ void ffma2(u64& d, u64 a, u64 b) {
    asm("fma.rn.f32x2 %0, %1, %2, %0;" : "+l"(d) : "l"(a), "l"(b));
}
__device__ __forceinline__ float2 unpack2(u64 v) {
    float2 r;
    asm("mov.b64 {%0, %1}, %2;" : "=f"(r.x), "=f"(r.y) : "l"(v));
    return r;
}

__device__ __forceinline__ float tanh_fast(float x) {
    float e = __expf(2.0f * x);
    return 1.0f - 2.0f / (e + 1.0f);
}

// ---------------------------------------------------------------------------
// Fused GEMM: C[M,N] = act(A[M,K] @ W[N,K]^T + bias), row-major, fp32.
// 16x16 thread grid, strided register tile. Inner loop uses packed f32x2
// FMAs: each accumulator holds (even-k partial, odd-k partial); summed in
// the epilogue. Deterministic fixed summation order.
// ---------------------------------------------------------------------------
template<int BM, int BN, int BK, int TM, int TN, bool TANH>
__global__ __launch_bounds__(256)
void gemm_bias_act(const float* __restrict__ A, const float* __restrict__ W,
                   const float* __restrict__ bias, float* __restrict__ C,
                   int M, int N, int K)
{
    constexpr int SK = BK + 4;          // pad: keeps 16B alignment, spreads banks
    __shared__ float sA[BM * SK];
    __shared__ float sB[BN * SK];

    const int tid = threadIdx.x;
    const int tx  = tid & 15;
    const int ty  = tid >> 4;
    const int m0  = blockIdx.y * BM;
    const int n0  = blockIdx.x * BN;

    constexpr int C4 = BK / 4;
    constexpr int LA = (BM * C4) / 256;
    constexpr int LB = (BN * C4) / 256;

    u64 acc2[TM][TN];
#pragma unroll
    for (int i = 0; i < TM; i++)
#pragma unroll
        for (int j = 0; j < TN; j++) acc2[i][j] = 0ull;   // (0.0f, 0.0f)

#pragma unroll 1
    for (int k0 = 0; k0 < K; k0 += BK) {
        __syncthreads();
#pragma unroll
        for (int q = 0; q < LA; q++) {
            int id = tid + 256 * q;
            int r = id / C4, c = id % C4;
            *(float4*)&sA[r * SK + c * 4] =
                *(const float4*)&A[(size_t)(m0 + r) * K + k0 + c * 4];
        }
#pragma unroll
        for (int q = 0; q < LB; q++) {
            int id = tid + 256 * q;
            int r = id / C4, c = id % C4;
            *(float4*)&sB[r * SK + c * 4] =
                *(const float4*)&W[(size_t)(n0 + r) * K + k0 + c * 4];
        }
        __syncthreads();
#pragma unroll
        for (int c = 0; c < C4; c++) {
            ulonglong2 a[TM], b[TN];   // 4 floats = 2 packed f32 pairs each
#pragma unroll
            for (int ii = 0; ii < TM; ii++)
                a[ii] = *(const ulonglong2*)&sA[(ty + 16 * ii) * SK + c * 4];
#pragma unroll
            for (int jj = 0; jj < TN; jj++)
                b[jj] = *(const ulonglong2*)&sB[(tx + 16 * jj) * SK + c * 4];
#pragma unroll
            for (int ii = 0; ii < TM; ii++)
#pragma unroll
                for (int jj = 0; jj < TN; jj++) {
                    ffma2(acc2[ii][jj], a[ii].x, b[jj].x);
                    ffma2(acc2[ii][jj], a[ii].y, b[jj].y);
                }
        }
    }

    float bl[TN];
#pragma unroll
    for (int jj = 0; jj < TN; jj++) bl[jj] = bias[n0 + tx + 16 * jj];
#pragma unroll
    for (int ii = 0; ii < TM; ii++) {
        const int m = m0 + ty + 16 * ii;
#pragma unroll
        for (int jj = 0; jj < TN; jj++) {
            float2 p = unpack2(acc2[ii][jj]);
            float v = p.x + p.y + bl[jj];
            if (TANH) v = tanh_fast(v);
            C[(size_t)m * N + n0 + tx + 16 * jj] = v;
        }
    }
}

// ---------------------------------------------------------------------------
// Row-normalize: normed[r] = out[r] / (||out[r]|| + 1e-12). One warp per row.
// ---------------------------------------------------------------------------
__global__ __launch_bounds__(256)
void normalize_kernel(const float* __restrict__ out, float* __restrict__ normed)
{
    const int row  = blockIdx.x * 8 + (threadIdx.x >> 5);
    const int lane = threadIdx.x & 31;
    float v0 = out[(size_t)row * D_OUT + lane];
    float v1 = out[(size_t)row * D_OUT + lane + 32];
    float s = v0 * v0 + v1 * v1;
#pragma unroll
    for (int off = 16; off > 0; off >>= 1)
        s += __shfl_xor_sync(0xffffffffu, s, off);
    float inv = 1.0f / (sqrtf(s) + 1e-12f);
    normed[(size_t)row * D_OUT + lane]      = v0 * inv;
    normed[(size_t)row * D_OUT + lane + 32] = v1 * inv;
}

// ---------------------------------------------------------------------------
// Pairwise fidelity + adjacency @ out, fused. One CTA owns 64 i-rows, loops
// over 128 j-tiles. Dot tile now uses packed f32x2 FMAs (2x throughput);
// threshold and sparse bitmask-gather unchanged (deterministic, no float
// atomics — each (row, 16-dim segment) owned by exactly one thread).
// ---------------------------------------------------------------------------
#define PAIR_SMEM_BYTES ((64*64 + 2*64*68) * 4 + 128 * 4)

__global__ __launch_bounds__(256)
void pair_adj_kernel(const float* __restrict__ normed,
                     const float* __restrict__ out,
                     float* __restrict__ result)
{
    extern __shared__ float sm[];
    float*    sNi   = sm;                       // [64][64]  (broadcast reads)
    float*    sNj   = sm + 64 * 64;             // [64][68]  padded
    float*    sOutj = sNj + 64 * 68;            // [64][68]
    unsigned* sMask = (unsigned*)(sOutj + 64 * 68); // [64][2]

    const int tid = threadIdx.x;
    const int tx  = tid & 15;
    const int ty  = tid >> 4;
    const int i0  = blockIdx.x * 64;

#pragma unroll
    for (int q = 0; q < 4; q++) {
        int id = tid + 256 * q;
        int r = id >> 4, c = id & 15;
        *(float4*)&sNi[r * 64 + c * 4] =
            *(const float4*)&normed[(size_t)(i0 + r) * 64 + c * 4];
    }

    float racc[16];
#pragma unroll
    for (int u = 0; u < 16; u++) racc[u] = 0.0f;
    const int irow = tid >> 2;
    const int seg  = (tid & 3) * 16;

#pragma unroll 1
    for (int jt = 0; jt < B_ROWS / 64; jt++) {
        const int j0 = jt * 64;
        __syncthreads();
#pragma unroll
        for (int q = 0; q < 4; q++) {
            int id = tid + 256 * q;
            int r = id >> 4, c = id & 15;
            *(float4*)&sNj[r * 68 + c * 4] =
                *(const float4*)&normed[(size_t)(j0 + r) * 64 + c * 4];
            *(float4*)&sOutj[r * 68 + c * 4] =
                *(const float4*)&out[(size_t)(j0 + r) * 64 + c * 4];
        }
        if (tid < 128) sMask[tid] = 0u;
        __syncthreads();

        // ---- dot tile via packed f32x2 FMAs ----
        u64 d2[4][4];
#pragma unroll
        for (int ii = 0; ii < 4; ii++)
#pragma unroll
            for (int jj = 0; jj < 4; jj++) d2[ii][jj] = 0ull;
#pragma unroll
        for (int c = 0; c < 16; c++) {
            ulonglong2 a[4], b[4];
#pragma unroll
            for (int ii = 0; ii < 4; ii++)
                a[ii] = *(const ulonglong2*)&sNi[(ty + 16 * ii) * 64 + c * 4];
#pragma unroll
            for (int jj = 0; jj < 4; jj++)
                b[jj] = *(const ulonglong2*)&sNj[(tx + 16 * jj) * 68 + c * 4];
#pragma unroll
            for (int ii = 0; ii < 4; ii++)
#pragma unroll
                for (int jj = 0; jj < 4; jj++) {
                    ffma2(d2[ii][jj], a[ii].x, b[jj].x);
                    ffma2(d2[ii][jj], a[ii].y, b[jj].y);
                }
        }

        // ---- threshold -> shared bitmasks ----
#pragma unroll
        for (int ii = 0; ii < 4; ii++) {
            const int il = ty + 16 * ii;
            const int gi = i0 + il;
            unsigned w0 = 0u, w1 = 0u;
#pragma unroll
            for (int jj = 0; jj < 4; jj++) {
                const int jl = tx + 16 * jj;
                float2 p = unpack2(d2[ii][jj]);
                const float dv = p.x + p.y;
                const bool e = (dv * dv >= 0.9f) && (gi != (j0 + jl));
                const unsigned bit = e ? (1u << (jl & 31)) : 0u;
                if (jj < 2) w0 |= bit; else w1 |= bit;
            }
            if (w0) atomicOr(&sMask[il * 2 + 0], w0);
            if (w1) atomicOr(&sMask[il * 2 + 1], w1);
        }
        __syncthreads();

        // ---- sparse gather over set bits ----
        unsigned mw0 = sMask[irow * 2 + 0];
        unsigned mw1 = sMask[irow * 2 + 1];
        while (mw0) {
            const int j = __ffs((int)mw0) - 1;
            mw0 &= mw0 - 1;
            const float* o = &sOutj[j * 68 + seg];
#pragma unroll
            for (int u = 0; u < 4; u++) {
                float4 v = *(const float4*)&o[u * 4];
                racc[u * 4 + 0] += v.x; racc[u * 4 + 1] += v.y;
                racc[u * 4 + 2] += v.z; racc[u * 4 + 3] += v.w;
            }
        }
        while (mw1) {
            const int j = 32 + __ffs((int)mw1) - 1;
            mw1 &= mw1 - 1;
            const float* o = &sOutj[j * 68 + seg];
#pragma unroll
            for (int u = 0; u < 4; u++) {
                float4 v = *(const float4*)&o[u * 4];
                racc[u * 4 + 0] += v.x; racc[u * 4 + 1] += v.y;
                racc[u * 4 + 2] += v.z; racc[u * 4 + 3] += v.w;
            }
        }
    }

    const int gi = i0 + irow;
#pragma unroll
    for (int u = 0; u < 4; u++) {
        float4 v = make_float4(racc[u * 4 + 0], racc[u * 4 + 1],
                               racc[u * 4 + 2], racc[u * 4 + 3]);
        *(float4*)&result[(size_t)gi * 64 + seg + u * 4] = v;
    }
}

// ---------------------------------------------------------------------------
extern "C" void kernel_launch(void* const* d_in, const int* in_sizes, int n_in,
                              void* d_out, int out_size)
{
    const float* x  = (const float*)d_in[0];
    const float* W1 = (const float*)d_in[1];
    const float* b1 = (const float*)d_in[2];
    const float* W2 = (const float*)d_in[3];
    const float* b2 = (const float*)d_in[4];
    const float* W3 = (const float*)d_in[5];
    const float* b3 = (const float*)d_in[6];
    float* result = (float*)d_out;

    float *h1, *h2, *o, *nr;
    cudaGetSymbolAddress((void**)&h1, g_h1);
    cudaGetSymbolAddress((void**)&h2, g_h2);
    cudaGetSymbolAddress((void**)&o,  g_out);
    cudaGetSymbolAddress((void**)&nr, g_normed);

    gemm_bias_act<128, 64, 32, 8, 4, true>
        <<<dim3(H1DIM / 64, B_ROWS / 128), 256>>>(x, W1, b1, h1, B_ROWS, H1DIM, D_IN);
    gemm_bias_act<128, 64, 32, 8, 4, true>
        <<<dim3(H2DIM / 64, B_ROWS / 128), 256>>>(h1, W2, b2, h2, B_ROWS, H2DIM, H1DIM);
    gemm_bias_act<64, 64, 32, 4, 4, false>
        <<<dim3(D_OUT / 64, B_ROWS / 64), 256>>>(h2, W3, b3, o, B_ROWS, D_OUT, H2DIM);

    normalize_kernel<<<B_ROWS / 8, 256>>>(o, nr);

    cudaFuncSetAttribute(pair_adj_kernel,
                         cudaFuncAttributeMaxDynamicSharedMemorySize,
                         PAIR_SMEM_BYTES);
    pair_adj_kernel<<<B_ROWS / 64, 256, PAIR_SMEM_BYTES>>>(nr, o, result);
}